// round 13
// baseline (speedup 1.0000x reference)
#include <cuda_runtime.h>
#include <cstdint>

// Segment mean pooling: x [524288,128] f32, pointer [1025] i32 -> out [1024,128] f32.
//
// Step 1: cudaMemsetAsync(out, 0) (graph-capturable memset node).
// Step 2: grid 1024 x 512-row chunks; load engine = cp.async.cg -> smem,
//   3 buffers x 8KB stages, depth-2 pipeline (~112KB in flight per SM vs
//   ~57KB register-bound LDG) to attack the 25% DRAM-idle seen in R10.
//   R12 bug fixed: the LAST stage must use wait_group 0 (only one group
//   pending there; wait_group 1 returned before the copy landed).
//   Consumers read their own smem slots and accumulate float4 partials; at
//   each CTA-uniform segment boundary: smem-reduce 8 warps -> 1, warp 0
//   scalar-atomicAdds inv-scaled partials into out (sum == mean).

#define D_FEAT 128
#define D4 (D_FEAT / 4)      // 32 float4 per row
#define CHUNK 512            // rows per CTA (n_rows % CHUNK == 0)
#define SROWS 16             // rows per stage (8 KB)
#define NSTAGE 32            // CHUNK / SROWS
#define NBUF 3

__device__ __forceinline__ void cp_async16(uint32_t dst_smem, const float4* src) {
    asm volatile("cp.async.cg.shared.global [%0], [%1], 16;\n"
                 :: "r"(dst_smem), "l"(src));
}
__device__ __forceinline__ void cp_commit() {
    asm volatile("cp.async.commit_group;\n" ::: "memory");
}
__device__ __forceinline__ void cp_wait1() {
    asm volatile("cp.async.wait_group 1;\n" ::: "memory");
}
__device__ __forceinline__ void cp_wait0() {
    asm volatile("cp.async.wait_group 0;\n" ::: "memory");
}

__global__ __launch_bounds__(256) void seg_accum_kernel(
    const float4* __restrict__ x4,
    const int* __restrict__ ptr,
    float* __restrict__ out,
    int n_rows, int n_segs)
{
    __shared__ float4 buf[NBUF][SROWS][D4];   // 24 KB
    __shared__ float4 sred[8][D4];            // 4 KB

    const int base = blockIdx.x * CHUNK;
    const int c4 = threadIdx.x & 31;          // float4 column 0..31
    const int r  = threadIdx.x >> 5;          // row lane 0..7

    uint32_t buf_base;
    {
        const void* p = &buf[0][0][0];
        asm("{ .reg .u64 t; cvta.to.shared.u64 t, %1; cvt.u32.u64 %0, t; }"
            : "=r"(buf_base) : "l"(p));
    }
    const uint32_t slot0 = (uint32_t)((r * D4 + c4) * 16);
    const uint32_t slot1 = (uint32_t)(((r + 8) * D4 + c4) * 16);

    auto issue = [&](int s) {
        const int row0 = base + s * SROWS + r;
        const uint32_t b = buf_base + (uint32_t)((s % NBUF) * SROWS * D4 * 16);
        cp_async16(b + slot0, x4 + (size_t)row0 * D4 + c4);
        cp_async16(b + slot1, x4 + (size_t)(row0 + 8) * D4 + c4);
        cp_commit();
    };

    // First segment overlapping the chunk (CTA-uniform -> broadcast hits).
    int lo = 0, hi = n_segs - 1;
    while (lo < hi) {
        int mid = (lo + hi + 1) >> 1;
        if (__ldg(ptr + mid) <= base) lo = mid; else hi = mid - 1;
    }
    int seg = lo;
    int seg_beg = __ldg(ptr + seg);
    int seg_end = __ldg(ptr + seg + 1);

    float4 acc = make_float4(0.f, 0.f, 0.f, 0.f);

    auto flush = [&]() {
        sred[r][c4] = acc;
        __syncthreads();
        if (r == 0) {
            float4 t = sred[0][c4];
            #pragma unroll
            for (int i = 1; i < 8; i++) {
                const float4 v = sred[i][c4];
                t.x += v.x; t.y += v.y; t.z += v.z; t.w += v.w;
            }
            const int cnt = seg_end - seg_beg;
            const float inv = 1.0f / (float)(cnt > 0 ? cnt : 1);
            float* o = out + (size_t)seg * D_FEAT + c4 * 4;
            atomicAdd(o + 0, t.x * inv);
            atomicAdd(o + 1, t.y * inv);
            atomicAdd(o + 2, t.z * inv);
            atomicAdd(o + 3, t.w * inv);
        }
        __syncthreads();
        acc = make_float4(0.f, 0.f, 0.f, 0.f);
    };

    issue(0);
    issue(1);

    for (int s = 0; s < NSTAGE; s++) {
        // Stage s must be complete. For s < NSTAGE-1 two groups are pending
        // ({s, s+1}) -> wait_group 1 retires s. At the final stage only {s}
        // is pending -> wait_group 0 (the R12 bug).
        if (s + 1 < NSTAGE) cp_wait1(); else cp_wait0();
        __syncthreads();

        const int sb = base + s * SROWS;
        const int se = sb + SROWS;
        const int row0 = sb + r;
        const int row1 = row0 + 8;
        const float4 v0 = buf[s % NBUF][r][c4];
        const float4 v1 = buf[s % NBUF][r + 8][c4];
        bool d0 = false, d1 = false;

        for (;;) {
            const int lim = min(seg_end, se);
            if (!d0 && row0 < lim) { acc.x += v0.x; acc.y += v0.y; acc.z += v0.z; acc.w += v0.w; d0 = true; }
            if (!d1 && row1 < lim) { acc.x += v1.x; acc.y += v1.y; acc.z += v1.z; acc.w += v1.w; d1 = true; }
            if (seg_end >= se) break;
            flush();
            seg++;
            seg_beg = __ldg(ptr + seg);
            seg_end = __ldg(ptr + seg + 1);
        }

        __syncthreads();          // all reads of buf[s%NBUF] done
        if (s + 2 < NSTAGE) issue(s + 2);
    }

    flush();   // residual partial for the segment spanning the chunk end
}

extern "C" void kernel_launch(void* const* d_in, const int* in_sizes, int n_in,
                              void* d_out, int out_size)
{
    const float4* x4  = (const float4*)d_in[0];
    const int*    ptr = (const int*)d_in[1];
    float*        out = (float*)d_out;

    const int n_rows = in_sizes[0] / D_FEAT;   // 524288
    const int n_segs = in_sizes[1] - 1;        // 1024

    cudaMemsetAsync(out, 0, (size_t)out_size * sizeof(float), 0);

    const int n_chunks = n_rows / CHUNK;       // 1024
    seg_accum_kernel<<<n_chunks, 256>>>(x4, ptr, out, n_rows, n_segs);
}

// round 14
// speedup vs baseline: 1.1337x; 1.1337x over previous
#include <cuda_runtime.h>

// Segment mean pooling: x [524288,128] f32, pointer [1025] i32 -> out [1024,128] f32.
//
// Converged design (R10 engine):
//   Step 1: cudaMemsetAsync(out, 0) — graph-capturable memset node.
//   Step 2: grid 1024 x 512-row chunks, 256 threads (8 warps x 32 float4-
//     columns, stride-8 rows, unroll 4, __ldcs streaming loads — read-once
//     data bypasses cache allocation). Per CTA-uniform segment intersection:
//     smem-reduce 8 warp partials -> 1, warp 0 flushes the inv-scaled partial
//     with ONE red.global.v4.f32 per lane (vs 4 scalar atomics; no return
//     trip). Sum of inv-scaled partials == segment mean.

#define D_FEAT 128
#define D4 (D_FEAT / 4)     // 32 float4 per row
#define CHUNK 512           // rows per CTA

__device__ __forceinline__ void red_add_v4(float* addr, float a, float b, float c, float d) {
    asm volatile("red.global.add.v4.f32 [%0], {%1, %2, %3, %4};"
                 :: "l"(addr), "f"(a), "f"(b), "f"(c), "f"(d) : "memory");
}

__global__ __launch_bounds__(256) void seg_accum_kernel(
    const float4* __restrict__ x4,
    const int* __restrict__ ptr,
    float* __restrict__ out,
    int n_rows, int n_segs)
{
    const int base = blockIdx.x * CHUNK;
    if (base >= n_rows) return;
    const int cend = min(base + CHUNK, n_rows);
    const int c4 = threadIdx.x & 31;   // float4 column 0..31
    const int r  = threadIdx.x >> 5;   // row-lane warp 0..7

    __shared__ float4 sred[8][D4];     // 4 KB

    // First segment overlapping the chunk (CTA-uniform -> broadcast L1 hits).
    int lo = 0, hi = n_segs - 1;
    while (lo < hi) {
        int mid = (lo + hi + 1) >> 1;
        if (__ldg(ptr + mid) <= base) lo = mid; else hi = mid - 1;
    }
    int seg = lo;

    for (;;) {
        const int seg_beg = __ldg(ptr + seg);
        const int seg_end = __ldg(ptr + seg + 1);
        const int s = max(seg_beg, base);
        const int e = min(seg_end, cend);

        float4 acc = make_float4(0.f, 0.f, 0.f, 0.f);
        #pragma unroll 4
        for (int row = s + r; row < e; row += 8) {
            const float4 v = __ldcs(x4 + (size_t)row * D4 + c4);  // streaming
            acc.x += v.x; acc.y += v.y; acc.z += v.z; acc.w += v.w;
        }

        // 8 warp-partials -> 1; warp 0 flushes the inv-scaled partial.
        sred[r][c4] = acc;
        __syncthreads();
        if (r == 0 && e > s) {
            #pragma unroll
            for (int i = 1; i < 8; i++) {
                const float4 v = sred[i][c4];
                acc.x += v.x; acc.y += v.y; acc.z += v.z; acc.w += v.w;
            }
            const float inv = 1.0f / (float)(seg_end - seg_beg);
            float* o = out + (size_t)seg * D_FEAT + c4 * 4;
            red_add_v4(o, acc.x * inv, acc.y * inv, acc.z * inv, acc.w * inv);
        }
        if (seg_end >= cend) break;
        seg++;
        __syncthreads();   // sred reuse safety
    }
}

extern "C" void kernel_launch(void* const* d_in, const int* in_sizes, int n_in,
                              void* d_out, int out_size)
{
    const float4* x4  = (const float4*)d_in[0];
    const int*    ptr = (const int*)d_in[1];
    float*        out = (float*)d_out;

    const int n_rows = in_sizes[0] / D_FEAT;   // 524288
    const int n_segs = in_sizes[1] - 1;        // 1024

    cudaMemsetAsync(out, 0, (size_t)out_size * sizeof(float), 0);

    const int n_chunks = (n_rows + CHUNK - 1) / CHUNK;   // 1024
    seg_accum_kernel<<<n_chunks, 256>>>(x4, ptr, out, n_rows, n_segs);
}